// round 9
// baseline (speedup 1.0000x reference)
#include <cuda_runtime.h>
#include <cuda_fp16.h>

// Problem constants (fixed by dataset; code handles N <= MAXN)
#define MAXN 100352
#define MAXE 5000192
#define T_TILES 8
#define TILE_SZ 12544                 // MAXN / 8; 25088 B fp16 per tile
#define NK_MAX (T_TILES * MAXN + 1)   // (tile, dst) key space
#define SCAN_TILE 4096
#define CTAS_PER_TILE 37
#define GATHER_THREADS 256

// ---- scratch (static device globals; no allocation allowed) ----
__device__ int   g_count[NK_MAX];
__device__ int   g_off[NK_MAX];
__device__ int   g_cursor[NK_MAX];
__device__ unsigned int g_pay[MAXE];          // (dst<<14) | src_local
__device__ float g_agg[MAXN];
__device__ __align__(16) float4 g_nd[MAXN];   // {dinv, z0, z, pad}
__device__ __align__(16) __half g_y[MAXN];
__device__ int   g_tilesum[256];
__device__ int   g_is64;

// ---------------------------------------------------------------
// 0) zero counters + agg + detect edge dtype
__global__ void zero_detect_kernel(const unsigned int* e, int NK, int N) {
    int i = blockIdx.x * blockDim.x + threadIdx.x;
    if (i < NK) g_count[i] = 0;
    if (i < N)  g_agg[i] = 0.0f;
    if (blockIdx.x == 0 && threadIdx.x == 0) {
        int is64 = 1;
        #pragma unroll 1
        for (int k = 1; k < 1024; k += 2) {
            if (e[k] != 0u) { is64 = 0; break; }
        }
        g_is64 = is64;
    }
}

__device__ __forceinline__ int load_idx(const void* eidx, long long pos) {
    if (g_is64) return (int)((const long long*)eidx)[pos];
    return ((const int*)eidx)[pos];
}

// 1) histogram over (src_tile, dst) keys
__global__ void hist_kernel(const void* eidx, int E, int N) {
    int e = blockIdx.x * blockDim.x + threadIdx.x;
    if (e >= E) return;
    int s = load_idx(eidx, e);
    int d = load_idx(eidx, (long long)E + e);
    int t = s / TILE_SZ;
    atomicAdd(&g_count[t * N + d], 1);
}

// 2) scan pass A: per-tile totals over NK counters
__global__ void __launch_bounds__(1024, 1) scanA_kernel(int NK) {
    __shared__ int wsum[32];
    int t = threadIdx.x;
    int base = blockIdx.x * SCAN_TILE + t * 4;
    int s = 0;
    #pragma unroll
    for (int j = 0; j < 4; j++) {
        int i = base + j;
        if (i < NK) s += g_count[i];
    }
    #pragma unroll
    for (int o = 16; o; o >>= 1) s += __shfl_xor_sync(0xffffffffu, s, o);
    if ((t & 31) == 0) wsum[t >> 5] = s;
    __syncthreads();
    if (t < 32) {
        int v = wsum[t];
        #pragma unroll
        for (int o = 16; o; o >>= 1) v += __shfl_xor_sync(0xffffffffu, v, o);
        if (t == 0) g_tilesum[blockIdx.x] = v;
    }
}

// 3) scan pass C: exclusive scan -> g_off + g_cursor
__global__ void __launch_bounds__(1024, 1) scanC_kernel(int NK) {
    __shared__ int wsum[32];
    __shared__ int s_tileoff;
    int t = threadIdx.x;
    int lane = t & 31;
    int warp = t >> 5;

    if (t < 32) {
        int s = 0;
        for (int j = t; j < blockIdx.x; j += 32) s += g_tilesum[j];
        #pragma unroll
        for (int o = 16; o; o >>= 1) s += __shfl_xor_sync(0xffffffffu, s, o);
        if (t == 0) s_tileoff = s;
    }

    int base = blockIdx.x * SCAN_TILE + t * 4;
    int c[4];
    #pragma unroll
    for (int j = 0; j < 4; j++) {
        int i = base + j;
        c[j] = (i < NK) ? g_count[i] : 0;
    }
    int local = c[0] + c[1] + c[2] + c[3];

    int inc = local;
    #pragma unroll
    for (int o = 1; o < 32; o <<= 1) {
        int v = __shfl_up_sync(0xffffffffu, inc, o);
        if (lane >= o) inc += v;
    }
    if (lane == 31) wsum[warp] = inc;
    __syncthreads();
    if (t < 32) {
        int v = wsum[t];
        int iv = v;
        #pragma unroll
        for (int o = 1; o < 32; o <<= 1) {
            int u = __shfl_up_sync(0xffffffffu, iv, o);
            if (lane >= o) iv += u;
        }
        wsum[t] = iv - v;
    }
    __syncthreads();
    int off = s_tileoff + wsum[warp] + (inc - local);
    #pragma unroll
    for (int j = 0; j < 4; j++) {
        int i = base + j;
        if (i < NK) {
            g_off[i] = off;
            g_cursor[i] = off;
            off += c[j];
        }
    }
}

// 4) placement: payload = (dst << 14) | src_local, sorted by (src_tile, dst)
__global__ void place_kernel(const void* eidx, int E, int N) {
    int e = blockIdx.x * blockDim.x + threadIdx.x;
    if (e >= E) return;
    int s = load_idx(eidx, e);
    int d = load_idx(eidx, (long long)E + e);
    int t = s / TILE_SZ;
    int idx = atomicAdd(&g_cursor[t * N + d], 1);
    g_pay[idx] = ((unsigned)d << 14) | (unsigned)(s - t * TILE_SZ);
}

// 5) encoder: deg = sum_t count[t*N+i]; z0 = MLP(x); nd = {dinv, z0, z0};
//    y = fp16(dinv * z0)
__global__ void encoder_kernel(const float* __restrict__ x,
                               const float* __restrict__ W1, const float* __restrict__ b1,
                               const float* __restrict__ W2, const float* __restrict__ b2,
                               const float* __restrict__ W3, int N) {
    __shared__ float sW2[256], sW1[16], sb1[16], sb2[16], sW3[16];
    int t = threadIdx.x;
    if (t < 256) sW2[t] = W2[t];
    if (t < 16) { sW1[t] = W1[t]; sb1[t] = b1[t]; sb2[t] = b2[t]; sW3[t] = W3[t]; }
    __syncthreads();
    int i = blockIdx.x * blockDim.x + t;
    if (i >= N) return;
    int deg = 0;
    #pragma unroll
    for (int tt = 0; tt < T_TILES; tt++) deg += __ldg(&g_count[tt * N + i]);
    float di = rsqrtf((float)deg + 1.0f);

    float xv = __ldg(&x[i]);
    float h1[16];
    #pragma unroll
    for (int q = 0; q < 16; q++) h1[q] = fmaxf(xv * sW1[q] + sb1[q], 0.0f);
    float z = 0.0f;
    #pragma unroll
    for (int q = 0; q < 16; q++) {
        float a = sb2[q];
        #pragma unroll
        for (int r = 0; r < 16; r++) a = fmaf(h1[r], sW2[r * 16 + q], a);
        z = fmaf(fmaxf(a, 0.0f), sW3[q], z);
    }
    g_nd[i] = make_float4(di, z, z, 0.0f);
    g_y[i] = __float2half(di * z);
}

// 6) gather: stage tile y in SMEM, edge-parallel LDS gathers,
//    warp-segmented reduction on sorted dst, sparse float atomics to agg.
__global__ void __launch_bounds__(GATHER_THREADS)
gather_kernel(int N, int E) {
    __shared__ __half sy[TILE_SZ];
    int tile = blockIdx.x / CTAS_PER_TILE;
    int cib  = blockIdx.x % CTAS_PER_TILE;
    int t = threadIdx.x;
    int tbase = tile * TILE_SZ;
    int cnt = min(TILE_SZ, N - tbase);

    // stage tile's y (16B vectors)
    {
        const uint4* src = (const uint4*)(g_y + tbase);
        uint4* dst = (uint4*)sy;
        int nv = (cnt + 7) >> 3;
        #pragma unroll 1
        for (int i = t; i < nv; i += GATHER_THREADS) dst[i] = src[i];
    }
    __syncthreads();

    int beg = __ldg(&g_off[tile * N]);
    int end = (tile == T_TILES - 1) ? E : __ldg(&g_off[(tile + 1) * N]);
    int lane = t & 31;
    int stride = CTAS_PER_TILE * GATHER_THREADS;

    #pragma unroll 1
    for (int base = beg + cib * GATHER_THREADS + (t & ~31); base < end; base += stride) {
        int e = base + lane;
        bool valid = e < end;
        unsigned p = valid ? g_pay[e] : 0u;
        unsigned d = p >> 14;
        float v = valid ? __half2float(sy[p & 0x3FFFu]) : 0.0f;
        unsigned key = valid ? d : 0xFFFFFFFFu;
        // segmented inclusive sum over sorted keys
        #pragma unroll
        for (int o = 1; o < 32; o <<= 1) {
            float uv = __shfl_up_sync(0xffffffffu, v, o);
            unsigned uk = __shfl_up_sync(0xffffffffu, key, o);
            if (lane >= o && uk == key) v += uv;
        }
        unsigned nk = __shfl_down_sync(0xffffffffu, key, 1);
        bool tail = (lane == 31) || (nk != key);
        if (valid && tail) atomicAdd(&g_agg[d], v);
    }
}

// 7) combine: z' = 0.9*(dinv*agg + dinv^2*z) + 0.1*z0; re-zero agg
__global__ void combine_kernel(const float* __restrict__ b3,
                               float* __restrict__ out, int k, int N) {
    int i = blockIdx.x * blockDim.x + threadIdx.x;
    if (i >= N) return;
    float a = g_agg[i];
    g_agg[i] = 0.0f;
    float4 nd = g_nd[i];
    float di = nd.x;
    float zn = fmaf(0.9f, fmaf(di, a, di * di * nd.z), 0.1f * nd.y);
    g_nd[i].z = zn;
    if (k < 9) g_y[i] = __float2half(di * zn);
    else       out[i] = zn + __ldg(&b3[0]);
}

extern "C" void kernel_launch(void* const* d_in, const int* in_sizes, int n_in,
                              void* d_out, int out_size) {
    const float* x  = (const float*)d_in[0];
    const void*  ei = d_in[1];
    const float* W1 = (const float*)d_in[2];
    const float* b1 = (const float*)d_in[3];
    const float* W2 = (const float*)d_in[4];
    const float* b2 = (const float*)d_in[5];
    const float* W3 = (const float*)d_in[6];
    const float* b3 = (const float*)d_in[7];
    float* out = (float*)d_out;

    int N = in_sizes[0];          // x is [N,1]
    int E = in_sizes[1] / 2;      // edge_index is [2,E]
    int NK = T_TILES * N;

    int nb  = (N + 255) / 256;
    int nkb = (NK + 255) / 256;
    int eb  = (E + 255) / 256;
    int ntilesK = (NK + SCAN_TILE - 1) / SCAN_TILE;

    // occupancy hint: prefer max shared carveout so 8 gather CTAs fit per SM
    cudaFuncSetAttribute(gather_kernel,
                         cudaFuncAttributePreferredSharedMemoryCarveout, 100);

    zero_detect_kernel<<<nkb, 256>>>((const unsigned int*)ei, NK, N);
    hist_kernel<<<eb, 256>>>(ei, E, N);
    scanA_kernel<<<ntilesK, 1024>>>(NK);
    scanC_kernel<<<ntilesK, 1024>>>(NK);
    place_kernel<<<eb, 256>>>(ei, E, N);
    encoder_kernel<<<nb, 256>>>(x, W1, b1, W2, b2, W3, N);

    // K = 10 iterations: gather (tiled SMEM) + combine
    for (int k = 0; k < 10; k++) {
        gather_kernel<<<T_TILES * CTAS_PER_TILE, GATHER_THREADS>>>(N, E);
        combine_kernel<<<nb, 256>>>(b3, out, k, N);
    }
}

// round 10
// speedup vs baseline: 1.4127x; 1.4127x over previous
#include <cuda_runtime.h>
#include <cuda_fp16.h>

// Problem constants (fixed by dataset; code handles N <= MAXN)
#define MAXN 100352
#define MAXE 5000192
#define T_TILES 8
#define TILE_SZ 12544                 // MAXN / 8; 25088 B fp16 per tile
#define NK_MAX (T_TILES * MAXN + 1)   // (tile, dst) key space
#define SCAN_TILE 4096
#define CTAS_PER_TILE 148
#define GATHER_THREADS 256

// ---- scratch (static device globals; no allocation allowed) ----
__device__ int   g_count[NK_MAX];
__device__ int   g_off[NK_MAX];
__device__ int   g_cursor[NK_MAX];
__device__ unsigned int g_pay[MAXE];          // (dst<<14) | src_local
__device__ float g_agg[MAXN];
__device__ __align__(16) float4 g_nd[MAXN];   // {dinv, z0, z, pad}
__device__ __align__(16) __half g_y[MAXN];
__device__ int   g_tilesum[256];
__device__ int   g_is64;

// ---------------------------------------------------------------
// 0) zero counters + agg + detect edge dtype
__global__ void zero_detect_kernel(const unsigned int* e, int NK, int N) {
    int i = blockIdx.x * blockDim.x + threadIdx.x;
    if (i < NK) g_count[i] = 0;
    if (i < N)  g_agg[i] = 0.0f;
    if (blockIdx.x == 0 && threadIdx.x == 0) {
        int is64 = 1;
        #pragma unroll 1
        for (int k = 1; k < 1024; k += 2) {
            if (e[k] != 0u) { is64 = 0; break; }
        }
        g_is64 = is64;
    }
}

__device__ __forceinline__ int load_idx(const void* eidx, long long pos) {
    if (g_is64) return (int)((const long long*)eidx)[pos];
    return ((const int*)eidx)[pos];
}

// 1) histogram over (src_tile, dst) keys
__global__ void hist_kernel(const void* eidx, int E, int N) {
    int e = blockIdx.x * blockDim.x + threadIdx.x;
    if (e >= E) return;
    int s = load_idx(eidx, e);
    int d = load_idx(eidx, (long long)E + e);
    int t = s / TILE_SZ;
    atomicAdd(&g_count[t * N + d], 1);
}

// 2) scan pass A: per-scan-tile totals over NK counters
__global__ void __launch_bounds__(1024, 1) scanA_kernel(int NK) {
    __shared__ int wsum[32];
    int t = threadIdx.x;
    int base = blockIdx.x * SCAN_TILE + t * 4;
    int s = 0;
    #pragma unroll
    for (int j = 0; j < 4; j++) {
        int i = base + j;
        if (i < NK) s += g_count[i];
    }
    #pragma unroll
    for (int o = 16; o; o >>= 1) s += __shfl_xor_sync(0xffffffffu, s, o);
    if ((t & 31) == 0) wsum[t >> 5] = s;
    __syncthreads();
    if (t < 32) {
        int v = wsum[t];
        #pragma unroll
        for (int o = 16; o; o >>= 1) v += __shfl_xor_sync(0xffffffffu, v, o);
        if (t == 0) g_tilesum[blockIdx.x] = v;
    }
}

// 3) scan pass C: exclusive scan -> g_off + g_cursor
__global__ void __launch_bounds__(1024, 1) scanC_kernel(int NK) {
    __shared__ int wsum[32];
    __shared__ int s_tileoff;
    int t = threadIdx.x;
    int lane = t & 31;
    int warp = t >> 5;

    if (t < 32) {
        int s = 0;
        for (int j = t; j < blockIdx.x; j += 32) s += g_tilesum[j];
        #pragma unroll
        for (int o = 16; o; o >>= 1) s += __shfl_xor_sync(0xffffffffu, s, o);
        if (t == 0) s_tileoff = s;
    }

    int base = blockIdx.x * SCAN_TILE + t * 4;
    int c[4];
    #pragma unroll
    for (int j = 0; j < 4; j++) {
        int i = base + j;
        c[j] = (i < NK) ? g_count[i] : 0;
    }
    int local = c[0] + c[1] + c[2] + c[3];

    int inc = local;
    #pragma unroll
    for (int o = 1; o < 32; o <<= 1) {
        int v = __shfl_up_sync(0xffffffffu, inc, o);
        if (lane >= o) inc += v;
    }
    if (lane == 31) wsum[warp] = inc;
    __syncthreads();
    if (t < 32) {
        int v = wsum[t];
        int iv = v;
        #pragma unroll
        for (int o = 1; o < 32; o <<= 1) {
            int u = __shfl_up_sync(0xffffffffu, iv, o);
            if (lane >= o) iv += u;
        }
        wsum[t] = iv - v;
    }
    __syncthreads();
    int off = s_tileoff + wsum[warp] + (inc - local);
    #pragma unroll
    for (int j = 0; j < 4; j++) {
        int i = base + j;
        if (i < NK) {
            g_off[i] = off;
            g_cursor[i] = off;
            off += c[j];
        }
    }
}

// 4) placement: payload = (dst << 14) | src_local, sorted by (src_tile, dst)
__global__ void place_kernel(const void* eidx, int E, int N) {
    int e = blockIdx.x * blockDim.x + threadIdx.x;
    if (e >= E) return;
    int s = load_idx(eidx, e);
    int d = load_idx(eidx, (long long)E + e);
    int t = s / TILE_SZ;
    int idx = atomicAdd(&g_cursor[t * N + d], 1);
    g_pay[idx] = ((unsigned)d << 14) | (unsigned)(s - t * TILE_SZ);
}

// 5) encoder: deg = sum_t count[t*N+i]; z0 = MLP(x); nd = {dinv, z0, z0};
//    y = fp16(dinv * z0)
__global__ void encoder_kernel(const float* __restrict__ x,
                               const float* __restrict__ W1, const float* __restrict__ b1,
                               const float* __restrict__ W2, const float* __restrict__ b2,
                               const float* __restrict__ W3, int N) {
    __shared__ float sW2[256], sW1[16], sb1[16], sb2[16], sW3[16];
    int t = threadIdx.x;
    if (t < 256) sW2[t] = W2[t];
    if (t < 16) { sW1[t] = W1[t]; sb1[t] = b1[t]; sb2[t] = b2[t]; sW3[t] = W3[t]; }
    __syncthreads();
    int i = blockIdx.x * blockDim.x + t;
    if (i >= N) return;
    int deg = 0;
    #pragma unroll
    for (int tt = 0; tt < T_TILES; tt++) deg += __ldg(&g_count[tt * N + i]);
    float di = rsqrtf((float)deg + 1.0f);

    float xv = __ldg(&x[i]);
    float h1[16];
    #pragma unroll
    for (int q = 0; q < 16; q++) h1[q] = fmaxf(xv * sW1[q] + sb1[q], 0.0f);
    float z = 0.0f;
    #pragma unroll
    for (int q = 0; q < 16; q++) {
        float a = sb2[q];
        #pragma unroll
        for (int r = 0; r < 16; r++) a = fmaf(h1[r], sW2[r * 16 + q], a);
        z = fmaf(fmaxf(a, 0.0f), sW3[q], z);
    }
    g_nd[i] = make_float4(di, z, z, 0.0f);
    g_y[i] = __float2half(di * z);
}

// 6) gather: stage tile y in SMEM (8 CTAs/SM -> full occupancy),
//    warp processes 128-edge blocks: 4 loads up-front (MLP), 4 rounds of
//    warp-segmented reduction on sorted dst, tail atomics to agg.
__global__ void __launch_bounds__(GATHER_THREADS, 8)
gather_kernel(int N, int E) {
    __shared__ __half sy[TILE_SZ];
    int tile = blockIdx.x / CTAS_PER_TILE;
    int cib  = blockIdx.x % CTAS_PER_TILE;
    int t = threadIdx.x;
    int tbase = tile * TILE_SZ;
    int cnt = min(TILE_SZ, N - tbase);

    // stage tile's y (16B vectors)
    {
        const uint4* src = (const uint4*)(g_y + tbase);
        uint4* dst = (uint4*)sy;
        int nv = (cnt + 7) >> 3;
        #pragma unroll 1
        for (int i = t; i < nv; i += GATHER_THREADS) dst[i] = src[i];
    }
    __syncthreads();

    int beg = __ldg(&g_off[tile * N]);
    int end = (tile == T_TILES - 1) ? E : __ldg(&g_off[(tile + 1) * N]);
    int lane = t & 31;
    int wig = cib * (GATHER_THREADS >> 5) + (t >> 5);   // warp-in-tile
    const int warps_per_tile = CTAS_PER_TILE * (GATHER_THREADS >> 5);
    const int stride = warps_per_tile * 128;

    #pragma unroll 1
    for (int base = beg + wig * 128; base < end; base += stride) {
        unsigned p[4];
        #pragma unroll
        for (int j = 0; j < 4; j++) {
            int e = base + j * 32 + lane;
            p[j] = (e < end) ? __ldcg(&g_pay[e]) : 0xFFFFFFFFu;
        }
        #pragma unroll
        for (int j = 0; j < 4; j++) {
            bool valid = p[j] != 0xFFFFFFFFu;
            unsigned key = p[j] >> 14;
            float v = valid ? __half2float(sy[p[j] & 0x3FFFu]) : 0.0f;
            // segmented inclusive sum over (sorted) keys
            #pragma unroll
            for (int o = 1; o < 32; o <<= 1) {
                float uv = __shfl_up_sync(0xffffffffu, v, o);
                unsigned uk = __shfl_up_sync(0xffffffffu, key, o);
                if (lane >= o && uk == key) v += uv;
            }
            unsigned nk = __shfl_down_sync(0xffffffffu, key, 1);
            bool tail = (lane == 31) || (nk != key);
            if (valid && tail) atomicAdd(&g_agg[key], v);
        }
    }
}

// 7) combine: z' = 0.9*(dinv*agg + dinv^2*z) + 0.1*z0; re-zero agg
__global__ void combine_kernel(const float* __restrict__ b3,
                               float* __restrict__ out, int k, int N) {
    int i = blockIdx.x * blockDim.x + threadIdx.x;
    if (i >= N) return;
    float a = g_agg[i];
    g_agg[i] = 0.0f;
    float4 nd = g_nd[i];
    float di = nd.x;
    float zn = fmaf(0.9f, fmaf(di, a, di * di * nd.z), 0.1f * nd.y);
    g_nd[i].z = zn;
    if (k < 9) g_y[i] = __float2half(di * zn);
    else       out[i] = zn + __ldg(&b3[0]);
}

extern "C" void kernel_launch(void* const* d_in, const int* in_sizes, int n_in,
                              void* d_out, int out_size) {
    const float* x  = (const float*)d_in[0];
    const void*  ei = d_in[1];
    const float* W1 = (const float*)d_in[2];
    const float* b1 = (const float*)d_in[3];
    const float* W2 = (const float*)d_in[4];
    const float* b2 = (const float*)d_in[5];
    const float* W3 = (const float*)d_in[6];
    const float* b3 = (const float*)d_in[7];
    float* out = (float*)d_out;

    int N = in_sizes[0];          // x is [N,1]
    int E = in_sizes[1] / 2;      // edge_index is [2,E]
    int NK = T_TILES * N;

    int nb  = (N + 255) / 256;
    int nkb = (NK + 255) / 256;
    int eb  = (E + 255) / 256;
    int ntilesK = (NK + SCAN_TILE - 1) / SCAN_TILE;

    cudaFuncSetAttribute(gather_kernel,
                         cudaFuncAttributePreferredSharedMemoryCarveout, 100);

    zero_detect_kernel<<<nkb, 256>>>((const unsigned int*)ei, NK, N);
    hist_kernel<<<eb, 256>>>(ei, E, N);
    scanA_kernel<<<ntilesK, 1024>>>(NK);
    scanC_kernel<<<ntilesK, 1024>>>(NK);
    place_kernel<<<eb, 256>>>(ei, E, N);
    encoder_kernel<<<nb, 256>>>(x, W1, b1, W2, b2, W3, N);

    // K = 10 iterations: gather (tiled SMEM, full occupancy) + combine
    for (int k = 0; k < 10; k++) {
        gather_kernel<<<T_TILES * CTAS_PER_TILE, GATHER_THREADS>>>(N, E);
        combine_kernel<<<nb, 256>>>(b3, out, k, N);
    }
}

// round 11
// speedup vs baseline: 1.7145x; 1.2136x over previous
#include <cuda_runtime.h>
#include <cuda_fp16.h>

// Problem constants (fixed by dataset; code handles N <= MAXN)
#define MAXN 100352
#define MAXE 5000192
#define T_TILES 8
#define TILE_SZ 12544                 // MAXN / 8; 25088 B fp16 per tile
#define NK_MAX (T_TILES * MAXN + 1)   // (tile, dst) key space
#define SCAN_TILE 4096
#define CTAS_PER_TILE 148
#define GATHER_THREADS 256

// ---- scratch (static device globals; no allocation allowed) ----
__device__ int   g_count[NK_MAX];
__device__ int   g_off[NK_MAX + 1];
__device__ int   g_cursor[NK_MAX];
__device__ unsigned short g_pay16[MAXE];      // src_local (tile,dst known from key)
__device__ float g_part[NK_MAX];              // per-(tile,dst) partial sums
__device__ __align__(16) float4 g_nd[MAXN];   // {dinv, z0, z, pad}
__device__ __align__(16) __half g_y[MAXN];
__device__ int   g_tilesum[256];
__device__ int   g_is64;

// ---------------------------------------------------------------
// 0) zero counters + detect edge dtype
__global__ void zero_detect_kernel(const unsigned int* e, int NK) {
    int i = blockIdx.x * blockDim.x + threadIdx.x;
    if (i < NK) g_count[i] = 0;
    if (blockIdx.x == 0 && threadIdx.x == 0) {
        int is64 = 1;
        #pragma unroll 1
        for (int k = 1; k < 1024; k += 2) {
            if (e[k] != 0u) { is64 = 0; break; }
        }
        g_is64 = is64;
    }
}

__device__ __forceinline__ int load_idx(const void* eidx, long long pos) {
    if (g_is64) return (int)((const long long*)eidx)[pos];
    return ((const int*)eidx)[pos];
}

// 1) histogram over (src_tile, dst) keys
__global__ void hist_kernel(const void* eidx, int E, int N) {
    int e = blockIdx.x * blockDim.x + threadIdx.x;
    if (e >= E) return;
    int s = load_idx(eidx, e);
    int d = load_idx(eidx, (long long)E + e);
    int t = s / TILE_SZ;
    atomicAdd(&g_count[t * N + d], 1);
}

// 2) scan pass A: per-scan-tile totals over NK counters
__global__ void __launch_bounds__(1024, 1) scanA_kernel(int NK) {
    __shared__ int wsum[32];
    int t = threadIdx.x;
    int base = blockIdx.x * SCAN_TILE + t * 4;
    int s = 0;
    #pragma unroll
    for (int j = 0; j < 4; j++) {
        int i = base + j;
        if (i < NK) s += g_count[i];
    }
    #pragma unroll
    for (int o = 16; o; o >>= 1) s += __shfl_xor_sync(0xffffffffu, s, o);
    if ((t & 31) == 0) wsum[t >> 5] = s;
    __syncthreads();
    if (t < 32) {
        int v = wsum[t];
        #pragma unroll
        for (int o = 16; o; o >>= 1) v += __shfl_xor_sync(0xffffffffu, v, o);
        if (t == 0) g_tilesum[blockIdx.x] = v;
    }
}

// 3) scan pass C: exclusive scan -> g_off + g_cursor (+ g_off[NK] = E)
__global__ void __launch_bounds__(1024, 1) scanC_kernel(int NK) {
    __shared__ int wsum[32];
    __shared__ int s_tileoff;
    int t = threadIdx.x;
    int lane = t & 31;
    int warp = t >> 5;

    if (t < 32) {
        int s = 0;
        for (int j = t; j < blockIdx.x; j += 32) s += g_tilesum[j];
        #pragma unroll
        for (int o = 16; o; o >>= 1) s += __shfl_xor_sync(0xffffffffu, s, o);
        if (t == 0) s_tileoff = s;
    }

    int base = blockIdx.x * SCAN_TILE + t * 4;
    int c[4];
    #pragma unroll
    for (int j = 0; j < 4; j++) {
        int i = base + j;
        c[j] = (i < NK) ? g_count[i] : 0;
    }
    int local = c[0] + c[1] + c[2] + c[3];

    int inc = local;
    #pragma unroll
    for (int o = 1; o < 32; o <<= 1) {
        int v = __shfl_up_sync(0xffffffffu, inc, o);
        if (lane >= o) inc += v;
    }
    if (lane == 31) wsum[warp] = inc;
    __syncthreads();
    if (t < 32) {
        int v = wsum[t];
        int iv = v;
        #pragma unroll
        for (int o = 1; o < 32; o <<= 1) {
            int u = __shfl_up_sync(0xffffffffu, iv, o);
            if (lane >= o) iv += u;
        }
        wsum[t] = iv - v;
    }
    __syncthreads();
    int off = s_tileoff + wsum[warp] + (inc - local);
    #pragma unroll
    for (int j = 0; j < 4; j++) {
        int i = base + j;
        if (i < NK) {
            g_off[i] = off;
            g_cursor[i] = off;
            off += c[j];
            if (i == NK - 1) g_off[NK] = off;
        }
    }
}

// 4) placement: pay16[pos] = src_local, positions sorted by (src_tile, dst)
__global__ void place_kernel(const void* eidx, int E, int N) {
    int e = blockIdx.x * blockDim.x + threadIdx.x;
    if (e >= E) return;
    int s = load_idx(eidx, e);
    int d = load_idx(eidx, (long long)E + e);
    int t = s / TILE_SZ;
    int idx = atomicAdd(&g_cursor[t * N + d], 1);
    g_pay16[idx] = (unsigned short)(s - t * TILE_SZ);
}

// 5) encoder: deg = sum_t count[t*N+i]; z0 = MLP(x); nd = {dinv, z0, z0};
//    y = fp16(dinv * z0)
__global__ void encoder_kernel(const float* __restrict__ x,
                               const float* __restrict__ W1, const float* __restrict__ b1,
                               const float* __restrict__ W2, const float* __restrict__ b2,
                               const float* __restrict__ W3, int N) {
    __shared__ float sW2[256], sW1[16], sb1[16], sb2[16], sW3[16];
    int t = threadIdx.x;
    if (t < 256) sW2[t] = W2[t];
    if (t < 16) { sW1[t] = W1[t]; sb1[t] = b1[t]; sb2[t] = b2[t]; sW3[t] = W3[t]; }
    __syncthreads();
    int i = blockIdx.x * blockDim.x + t;
    if (i >= N) return;
    int deg = 0;
    #pragma unroll
    for (int tt = 0; tt < T_TILES; tt++) deg += __ldg(&g_count[tt * N + i]);
    float di = rsqrtf((float)deg + 1.0f);

    float xv = __ldg(&x[i]);
    float h1[16];
    #pragma unroll
    for (int q = 0; q < 16; q++) h1[q] = fmaxf(xv * sW1[q] + sb1[q], 0.0f);
    float z = 0.0f;
    #pragma unroll
    for (int q = 0; q < 16; q++) {
        float a = sb2[q];
        #pragma unroll
        for (int r = 0; r < 16; r++) a = fmaf(h1[r], sW2[r * 16 + q], a);
        z = fmaf(fmaxf(a, 0.0f), sW3[q], z);
    }
    g_nd[i] = make_float4(di, z, z, 0.0f);
    g_y[i] = __float2half(di * z);
}

// 6) gather: stage tile y in SMEM (8 CTAs/SM), ONE THREAD PER (tile,dst) KEY:
//    serial LDS sum over the key's edge run, coalesced plain store to g_part.
//    No shuffles, no atomics.
__global__ void __launch_bounds__(GATHER_THREADS, 8)
gather_kernel(int N) {
    __shared__ __half sy[TILE_SZ];
    int tile = blockIdx.x / CTAS_PER_TILE;
    int cib  = blockIdx.x % CTAS_PER_TILE;
    int t = threadIdx.x;
    int tbase = tile * TILE_SZ;
    int cnt = min(TILE_SZ, N - tbase);

    // stage tile's y (16B vectors)
    {
        const uint4* src = (const uint4*)(g_y + tbase);
        uint4* dst = (uint4*)sy;
        int nv = (cnt + 7) >> 3;
        #pragma unroll 1
        for (int i = t; i < nv; i += GATHER_THREADS) dst[i] = src[i];
    }
    __syncthreads();

    const int kbase = tile * N;
    const int stride = CTAS_PER_TILE * GATHER_THREADS;

    #pragma unroll 1
    for (int d = cib * GATHER_THREADS + t; d < N; d += stride) {
        int k = kbase + d;
        int beg = __ldg(&g_off[k]);
        int end = __ldg(&g_off[k + 1]);
        float s = 0.0f;
        #pragma unroll 1
        for (int e = beg; e < end; e++)
            s += __half2float(sy[__ldg(&g_pay16[e])]);
        g_part[k] = s;            // coalesced across consecutive d
    }
}

// 7) combine: agg = sum_t part[t*N+i]; z' = 0.9*(dinv*agg + dinv^2*z) + 0.1*z0
__global__ void combine_kernel(const float* __restrict__ b3,
                               float* __restrict__ out, int k, int N) {
    int i = blockIdx.x * blockDim.x + threadIdx.x;
    if (i >= N) return;
    float a = 0.0f;
    #pragma unroll
    for (int tt = 0; tt < T_TILES; tt++) a += __ldg(&g_part[tt * N + i]);
    float4 nd = g_nd[i];
    float di = nd.x;
    float zn = fmaf(0.9f, fmaf(di, a, di * di * nd.z), 0.1f * nd.y);
    g_nd[i].z = zn;
    if (k < 9) g_y[i] = __float2half(di * zn);
    else       out[i] = zn + __ldg(&b3[0]);
}

extern "C" void kernel_launch(void* const* d_in, const int* in_sizes, int n_in,
                              void* d_out, int out_size) {
    const float* x  = (const float*)d_in[0];
    const void*  ei = d_in[1];
    const float* W1 = (const float*)d_in[2];
    const float* b1 = (const float*)d_in[3];
    const float* W2 = (const float*)d_in[4];
    const float* b2 = (const float*)d_in[5];
    const float* W3 = (const float*)d_in[6];
    const float* b3 = (const float*)d_in[7];
    float* out = (float*)d_out;

    int N = in_sizes[0];          // x is [N,1]
    int E = in_sizes[1] / 2;      // edge_index is [2,E]
    int NK = T_TILES * N;

    int nb  = (N + 255) / 256;
    int nkb = (NK + 255) / 256;
    int eb  = (E + 255) / 256;
    int ntilesK = (NK + SCAN_TILE - 1) / SCAN_TILE;

    cudaFuncSetAttribute(gather_kernel,
                         cudaFuncAttributePreferredSharedMemoryCarveout, 100);

    zero_detect_kernel<<<nkb, 256>>>((const unsigned int*)ei, NK);
    hist_kernel<<<eb, 256>>>(ei, E, N);
    scanA_kernel<<<ntilesK, 1024>>>(NK);
    scanC_kernel<<<ntilesK, 1024>>>(NK);
    place_kernel<<<eb, 256>>>(ei, E, N);
    encoder_kernel<<<nb, 256>>>(x, W1, b1, W2, b2, W3, N);

    // K = 10 iterations: gather (thread-per-key, tiled SMEM) + combine
    for (int k = 0; k < 10; k++) {
        gather_kernel<<<T_TILES * CTAS_PER_TILE, GATHER_THREADS>>>(N);
        combine_kernel<<<nb, 256>>>(b3, out, k, N);
    }
}

// round 12
// speedup vs baseline: 1.9610x; 1.1438x over previous
#include <cuda_runtime.h>
#include <cuda_fp16.h>

// Problem constants (fixed by dataset; code handles N <= MAXN)
#define MAXN 100352
#define MAXE 5000192
#define T_TILES 8
#define TILE_SZ 12544                 // MAXN / 8; 25088 B fp16 per tile
#define NK_MAX (T_TILES * MAXN + 1)   // (tile, dst) key space
#define SCAN_TILE 4096
#define CTAS_PER_TILE 37
#define GATHER_THREADS 1024

// ---- scratch (static device globals; no allocation allowed) ----
__device__ int   g_count[NK_MAX];
__device__ int   g_off[NK_MAX];
__device__ int   g_cursor[NK_MAX];
__device__ unsigned short g_pay16[MAXE];      // src_local (tile known from key)
__device__ float g_part[NK_MAX];              // per-(tile,dst) partial sums
__device__ __align__(16) float4 g_nd[MAXN];   // {dinv, z0, z, pad}
__device__ __align__(16) __half g_y[MAXN];
__device__ int   g_total;
__device__ int   g_is64;

// ---------------------------------------------------------------
// 0) zero counters + scan base + detect edge dtype
__global__ void zero_detect_kernel(const unsigned int* e, int NK) {
    int i = blockIdx.x * blockDim.x + threadIdx.x;
    if (i < NK) g_count[i] = 0;
    if (blockIdx.x == 0 && threadIdx.x == 0) {
        g_total = 0;
        int is64 = 1;
        #pragma unroll 1
        for (int k = 1; k < 1024; k += 2) {
            if (e[k] != 0u) { is64 = 0; break; }
        }
        g_is64 = is64;
    }
}

__device__ __forceinline__ int load_idx(const void* eidx, long long pos) {
    if (g_is64) return (int)((const long long*)eidx)[pos];
    return ((const int*)eidx)[pos];
}

// 1) histogram over (src_tile, dst) keys
__global__ void hist_kernel(const void* eidx, int E, int N) {
    int e = blockIdx.x * blockDim.x + threadIdx.x;
    if (e >= E) return;
    int s = load_idx(eidx, e);
    int d = load_idx(eidx, (long long)E + e);
    int t = s / TILE_SZ;
    atomicAdd(&g_count[t * N + d], 1);
}

// 2) single-pass scan: block-local exclusive scan + atomic global base.
//    Offsets form a valid (unordered) partition of [0, E); gather uses
//    end = off[k] + count[k], so global ordering is irrelevant.
__global__ void __launch_bounds__(1024, 1) scan_kernel(int NK) {
    __shared__ int wsum[32];
    __shared__ int s_base;
    int t = threadIdx.x;
    int lane = t & 31;
    int warp = t >> 5;

    int base = blockIdx.x * SCAN_TILE + t * 4;
    int c[4];
    if (base + 3 < NK) {
        int4 v4 = *reinterpret_cast<const int4*>(&g_count[base]);
        c[0] = v4.x; c[1] = v4.y; c[2] = v4.z; c[3] = v4.w;
    } else {
        #pragma unroll
        for (int j = 0; j < 4; j++) c[j] = (base + j < NK) ? g_count[base + j] : 0;
    }
    int local = c[0] + c[1] + c[2] + c[3];

    int inc = local;
    #pragma unroll
    for (int o = 1; o < 32; o <<= 1) {
        int v = __shfl_up_sync(0xffffffffu, inc, o);
        if (lane >= o) inc += v;
    }
    if (lane == 31) wsum[warp] = inc;
    __syncthreads();
    if (t < 32) {
        int v = wsum[t];
        int iv = v;
        #pragma unroll
        for (int o = 1; o < 32; o <<= 1) {
            int u = __shfl_up_sync(0xffffffffu, iv, o);
            if (lane >= o) iv += u;
        }
        wsum[t] = iv - v;                         // exclusive warp offsets
        if (t == 31) s_base = atomicAdd(&g_total, iv);  // block total -> base
    }
    __syncthreads();
    int off = s_base + wsum[warp] + (inc - local);
    #pragma unroll
    for (int j = 0; j < 4; j++) {
        int i = base + j;
        if (i < NK) {
            g_off[i] = off;
            g_cursor[i] = off;
            off += c[j];
        }
    }
}

// 3) placement: pay16[pos] = src_local, positions grouped per key
__global__ void place_kernel(const void* eidx, int E, int N) {
    int e = blockIdx.x * blockDim.x + threadIdx.x;
    if (e >= E) return;
    int s = load_idx(eidx, e);
    int d = load_idx(eidx, (long long)E + e);
    int t = s / TILE_SZ;
    int idx = atomicAdd(&g_cursor[t * N + d], 1);
    g_pay16[idx] = (unsigned short)(s - t * TILE_SZ);
}

// 4) encoder: deg = sum_t count[t*N+i]; z0 = MLP(x); nd = {dinv, z0, z0};
//    y = fp16(dinv * z0)
__global__ void encoder_kernel(const float* __restrict__ x,
                               const float* __restrict__ W1, const float* __restrict__ b1,
                               const float* __restrict__ W2, const float* __restrict__ b2,
                               const float* __restrict__ W3, int N) {
    __shared__ float sW2[256], sW1[16], sb1[16], sb2[16], sW3[16];
    int t = threadIdx.x;
    if (t < 256) sW2[t] = W2[t];
    if (t < 16) { sW1[t] = W1[t]; sb1[t] = b1[t]; sb2[t] = b2[t]; sW3[t] = W3[t]; }
    __syncthreads();
    int i = blockIdx.x * blockDim.x + t;
    if (i >= N) return;
    int deg = 0;
    #pragma unroll
    for (int tt = 0; tt < T_TILES; tt++) deg += __ldg(&g_count[tt * N + i]);
    float di = rsqrtf((float)deg + 1.0f);

    float xv = __ldg(&x[i]);
    float h1[16];
    #pragma unroll
    for (int q = 0; q < 16; q++) h1[q] = fmaxf(xv * sW1[q] + sb1[q], 0.0f);
    float z = 0.0f;
    #pragma unroll
    for (int q = 0; q < 16; q++) {
        float a = sb2[q];
        #pragma unroll
        for (int r = 0; r < 16; r++) a = fmaf(h1[r], sW2[r * 16 + q], a);
        z = fmaf(fmaxf(a, 0.0f), sW3[q], z);
    }
    g_nd[i] = make_float4(di, z, z, 0.0f);
    g_y[i] = __float2half(di * z);
}

// 5) gather: stage tile y in SMEM (1024-thr CTAs, 2/SM -> full occupancy,
//    4x less staging traffic), ONE THREAD PER (tile,dst) KEY:
//    serial LDS sum over the key's edge run, coalesced store to g_part.
__global__ void __launch_bounds__(GATHER_THREADS, 2)
gather_kernel(int N) {
    __shared__ __half sy[TILE_SZ];
    int tile = blockIdx.x / CTAS_PER_TILE;
    int cib  = blockIdx.x % CTAS_PER_TILE;
    int t = threadIdx.x;
    int tbase = tile * TILE_SZ;
    int cnt = min(TILE_SZ, N - tbase);

    // stage tile's y (16B vectors)
    {
        const uint4* src = (const uint4*)(g_y + tbase);
        uint4* dst = (uint4*)sy;
        int nv = (cnt + 7) >> 3;
        #pragma unroll 1
        for (int i = t; i < nv; i += GATHER_THREADS) dst[i] = src[i];
    }
    __syncthreads();

    const int kbase = tile * N;
    const int stride = CTAS_PER_TILE * GATHER_THREADS;

    #pragma unroll 1
    for (int d = cib * GATHER_THREADS + t; d < N; d += stride) {
        int k = kbase + d;
        int beg = __ldg(&g_off[k]);
        int end = beg + __ldg(&g_count[k]);
        float s = 0.0f;
        #pragma unroll 1
        for (int e = beg; e < end; e++)
            s += __half2float(sy[__ldg(&g_pay16[e])]);
        g_part[k] = s;            // coalesced across consecutive d
    }
}

// 6) combine: agg = sum_t part[t*N+i]; z' = 0.9*(dinv*agg + dinv^2*z) + 0.1*z0
__global__ void combine_kernel(const float* __restrict__ b3,
                               float* __restrict__ out, int k, int N) {
    int i = blockIdx.x * blockDim.x + threadIdx.x;
    if (i >= N) return;
    float a = 0.0f;
    #pragma unroll
    for (int tt = 0; tt < T_TILES; tt++) a += __ldg(&g_part[tt * N + i]);
    float4 nd = g_nd[i];
    float di = nd.x;
    float zn = fmaf(0.9f, fmaf(di, a, di * di * nd.z), 0.1f * nd.y);
    g_nd[i].z = zn;
    if (k < 9) g_y[i] = __float2half(di * zn);
    else       out[i] = zn + __ldg(&b3[0]);
}

extern "C" void kernel_launch(void* const* d_in, const int* in_sizes, int n_in,
                              void* d_out, int out_size) {
    const float* x  = (const float*)d_in[0];
    const void*  ei = d_in[1];
    const float* W1 = (const float*)d_in[2];
    const float* b1 = (const float*)d_in[3];
    const float* W2 = (const float*)d_in[4];
    const float* b2 = (const float*)d_in[5];
    const float* W3 = (const float*)d_in[6];
    const float* b3 = (const float*)d_in[7];
    float* out = (float*)d_out;

    int N = in_sizes[0];          // x is [N,1]
    int E = in_sizes[1] / 2;      // edge_index is [2,E]
    int NK = T_TILES * N;

    int nb  = (N + 255) / 256;
    int nkb = (NK + 255) / 256;
    int eb  = (E + 255) / 256;
    int ntilesK = (NK + SCAN_TILE - 1) / SCAN_TILE;

    zero_detect_kernel<<<nkb, 256>>>((const unsigned int*)ei, NK);
    hist_kernel<<<eb, 256>>>(ei, E, N);
    scan_kernel<<<ntilesK, 1024>>>(NK);
    place_kernel<<<eb, 256>>>(ei, E, N);
    encoder_kernel<<<nb, 256>>>(x, W1, b1, W2, b2, W3, N);

    // K = 10 iterations: gather (thread-per-key, tiled SMEM) + combine
    for (int k = 0; k < 10; k++) {
        gather_kernel<<<T_TILES * CTAS_PER_TILE, GATHER_THREADS>>>(N);
        combine_kernel<<<nb, 256>>>(b3, out, k, N);
    }
}